// round 6
// baseline (speedup 1.0000x reference)
#include <cuda_runtime.h>

#define S_LEN 128
#define NH 8
#define INF9 1.0e9f

// Weight fragments, prepped once per launch.
__device__ float g_Wf[3 * 8 * 2048];   // [z][h][kk8][nf4][lane32][2]
__device__ float g_Wof[8 * 2048];      // [h][kk4][nf8][lane32][2]

__device__ __forceinline__ float f2tf(float x) {
  unsigned r;
  asm("cvt.rna.tf32.f32 %0, %1;" : "=r"(r) : "f"(x));
  return __uint_as_float(r);
}

__device__ __forceinline__ void mma8(float4& c, float a0, float a1, float a2,
                                     float a3, float b0, float b1) {
  asm volatile(
      "mma.sync.aligned.m16n8k8.row.col.f32.tf32.tf32.f32 "
      "{%0,%1,%2,%3}, {%4,%5,%6,%7}, {%8,%9}, {%0,%1,%2,%3};"
      : "+f"(c.x), "+f"(c.y), "+f"(c.z), "+f"(c.w)
      : "r"(__float_as_uint(a0)), "r"(__float_as_uint(a1)),
        "r"(__float_as_uint(a2)), "r"(__float_as_uint(a3)),
        "r"(__float_as_uint(b0)), "r"(__float_as_uint(b1)));
}

// ---------------------------------------------------------------------------
// Prep: weights -> per-head lane-major B-fragment layouts (tf32, q pre-scaled)
// ---------------------------------------------------------------------------
__global__ void prep_kernel(const float* __restrict__ wq,
                            const float* __restrict__ wk,
                            const float* __restrict__ wv,
                            const float* __restrict__ wo) {
  const float scale = 0.17677669529663687f;  // 1/sqrt(32)
  for (int id = blockIdx.x * 256 + threadIdx.x; id < 65536; id += 64 * 256) {
    if (id < 49152) {
      int z = id / 16384, id2 = id % 16384;
      int p = id2 & 1, lane = (id2 >> 1) & 31, nf = (id2 >> 6) & 3,
          kk = (id2 >> 8) & 7, h = id2 >> 11;
      int r4 = lane >> 2, c4 = lane & 3;
      const float* w = (z == 0) ? wq : (z == 1) ? wk : wv;
      float v = w[(kk * 8 + c4 + 4 * p) * 256 + h * 32 + nf * 8 + r4];
      if (z == 0) v *= scale;
      g_Wf[id] = f2tf(v);
    } else {
      int id2 = id - 49152;
      int p = id2 & 1, lane = (id2 >> 1) & 31, nf = (id2 >> 6) & 7,
          kk = (id2 >> 9) & 3, h = id2 >> 11;
      int r4 = lane >> 2, c4 = lane & 3;
      g_Wof[id2] = f2tf(wo[(h * 32 + kk * 8 + c4 + 4 * p) * 64 + nf * 8 + r4]);
    }
  }
}

// ---------------------------------------------------------------------------
// Mega-fused kernel: one block per s, 512 threads (16 warps). Warp w owns
// 16 rows (w*16..w*16+15) for q and kv. All intermediates in SMEM/regs.
// ---------------------------------------------------------------------------
#define FUSED_SMEM (57600 * 4)

__global__ __launch_bounds__(512, 1) void fused_kernel(
    const float* __restrict__ xq, const float* __restrict__ xkv,
    const float* __restrict__ mask, const float* __restrict__ bias,
    const float* __restrict__ bo, float* __restrict__ outg) {
  extern __shared__ float sm[];
  float* Xq  = sm;            // [rt16][kk8][lane][4]  A-frags of input_q
  float* Xk  = sm + 16384;    // same for input_kv
  float* Wsm = sm + 32768;    // Wq|Wk|Wv|Wo frags (4 x 2048)
  float* Ks  = sm + 40960;    // [kt32][dd4][lane][2]
  float* Vs  = sm + 49152;    // [kc32][nf4][lane][2]
  float* ms  = sm + 57344;    // [256]

  const int tid = threadIdx.x;
  const int s = blockIdx.x;

  // Stage Xq, Xkv into A-frag layout (tf32)
  for (int i = tid; i < 4096; i += 512) {
    int row = i >> 4, k0 = (i & 15) * 4;
    float4 a = *(const float4*)(xq + (size_t)(s * 256 + row) * 64 + k0);
    float4 b = *(const float4*)(xkv + (size_t)(s * 256 + row) * 64 + k0);
    int rt = row >> 4, rr = row & 15;
    int r4s = rr & 7, eR = rr >> 3;
    int kk = k0 >> 3, half = (k0 >> 2) & 1;
    int off = ((rt * 8 + kk) * 32 + r4s * 4) * 4 + eR + 2 * half;
    Xq[off] = f2tf(a.x); Xq[off + 4] = f2tf(a.y);
    Xq[off + 8] = f2tf(a.z); Xq[off + 12] = f2tf(a.w);
    Xk[off] = f2tf(b.x); Xk[off + 4] = f2tf(b.y);
    Xk[off + 8] = f2tf(b.z); Xk[off + 12] = f2tf(b.w);
  }
  if (tid < 256) ms[tid] = (mask[s * 256 + tid] - 1.0f) * INF9;

  const int w = tid >> 5, lane = tid & 31;
  const int r4 = lane >> 2, c4 = lane & 3;
  const int src0 = (lane & ~3) | (c4 >> 1);
  const int src2 = src0 + 2;
  const bool odd = (c4 & 1);

  float4 oacc[8];  // output accum: rows w*16+{r4,r4+8}, 64 cols
#pragma unroll
  for (int j = 0; j < 8; j++) oacc[j] = make_float4(0.f, 0.f, 0.f, 0.f);

#pragma unroll 1
  for (int h = 0; h < NH; h++) {
    __syncthreads();  // prior head's SMEM reads done (also orders X staging)
    // Stage this head's weight frags (coalesced float4 copies)
    for (int i = tid; i < 2048; i += 512) {
      int z = i >> 9, wi = i & 511;
      float4 v = (z < 3) ? ((const float4*)g_Wf)[(z * 8 + h) * 512 + wi]
                         : ((const float4*)g_Wof)[h * 512 + wi];
      ((float4*)Wsm)[i] = v;
    }
    __syncthreads();

    // ---- Q = Xq @ Wq_h -> qa A-frags (regs only) ----
    float4 qa[4];
    {
      float4 acc[4];
#pragma unroll
      for (int j = 0; j < 4; j++) acc[j] = make_float4(0.f, 0.f, 0.f, 0.f);
#pragma unroll
      for (int kk = 0; kk < 8; kk++) {
        float4 A0 = *(float4*)(Xq + ((w * 8 + kk) * 32 + lane) * 4);
#pragma unroll
        for (int nf = 0; nf < 4; nf++) {
          float2 B = *(float2*)(Wsm + ((kk * 4 + nf) * 32 + lane) * 2);
          mma8(acc[nf], A0.x, A0.y, A0.z, A0.w, B.x, B.y);
        }
      }
#pragma unroll
      for (int dd = 0; dd < 4; dd++) {
        float p0 = f2tf(acc[dd].x), p1 = f2tf(acc[dd].y);
        float p2 = f2tf(acc[dd].z), p3 = f2tf(acc[dd].w);
        float t00 = __shfl_sync(0xffffffffu, p0, src0);
        float t01 = __shfl_sync(0xffffffffu, p1, src0);
        float t20 = __shfl_sync(0xffffffffu, p2, src0);
        float t21 = __shfl_sync(0xffffffffu, p3, src0);
        float u00 = __shfl_sync(0xffffffffu, p0, src2);
        float u01 = __shfl_sync(0xffffffffu, p1, src2);
        float u20 = __shfl_sync(0xffffffffu, p2, src2);
        float u21 = __shfl_sync(0xffffffffu, p3, src2);
        qa[dd] = make_float4(odd ? t01 : t00, odd ? t21 : t20,
                             odd ? u01 : u00, odd ? u21 : u20);
      }
    }

    // ---- K = Xkv @ Wk_h -> Ks scatter ----
    {
      float4 acc[4];
#pragma unroll
      for (int j = 0; j < 4; j++) acc[j] = make_float4(0.f, 0.f, 0.f, 0.f);
#pragma unroll
      for (int kk = 0; kk < 8; kk++) {
        float4 A0 = *(float4*)(Xk + ((w * 8 + kk) * 32 + lane) * 4);
#pragma unroll
        for (int nf = 0; nf < 4; nf++) {
          float2 B = *(float2*)(Wsm + 2048 + ((kk * 4 + nf) * 32 + lane) * 2);
          mma8(acc[nf], A0.x, A0.y, A0.z, A0.w, B.x, B.y);
        }
      }
#pragma unroll
      for (int nf = 0; nf < 4; nf++) {
        float vals[4] = {f2tf(acc[nf].x), f2tf(acc[nf].y),
                         f2tf(acc[nf].z), f2tf(acc[nf].w)};
#pragma unroll
        for (int e2 = 0; e2 < 4; e2++) {
          int eR = e2 >> 1, j = e2 & 1;
          int kvrow = w * 16 + r4 + 8 * eR;
          int dim = nf * 8 + 2 * c4 + j;
          int idx = (((kvrow >> 3) * 4 + nf) * 32 + r4 * 4 + (dim & 3)) * 2 +
                    ((dim >> 2) & 1);
          Ks[idx] = vals[e2];
        }
      }
    }

    // ---- V = Xkv @ Wv_h -> Vs scatter ----
    {
      float4 acc[4];
#pragma unroll
      for (int j = 0; j < 4; j++) acc[j] = make_float4(0.f, 0.f, 0.f, 0.f);
#pragma unroll
      for (int kk = 0; kk < 8; kk++) {
        float4 A0 = *(float4*)(Xk + ((w * 8 + kk) * 32 + lane) * 4);
#pragma unroll
        for (int nf = 0; nf < 4; nf++) {
          float2 B = *(float2*)(Wsm + 4096 + ((kk * 4 + nf) * 32 + lane) * 2);
          mma8(acc[nf], A0.x, A0.y, A0.z, A0.w, B.x, B.y);
        }
      }
#pragma unroll
      for (int nf = 0; nf < 4; nf++) {
        float vals[4] = {f2tf(acc[nf].x), f2tf(acc[nf].y),
                         f2tf(acc[nf].z), f2tf(acc[nf].w)};
#pragma unroll
        for (int e2 = 0; e2 < 4; e2++) {
          int eR = e2 >> 1, j = e2 & 1;
          int kvrow = w * 16 + r4 + 8 * eR;
          int dim = nf * 8 + 2 * c4 + j;
          int idx = (((kvrow >> 3) * 4 + (dim >> 3)) * 32 + (dim & 7) * 4 +
                     (kvrow & 3)) * 2 + ((kvrow >> 2) & 1);
          Vs[idx] = vals[e2];
        }
      }
    }
    __syncthreads();  // K/V tiles ready

    // ---- attention over this head ----
    float4 o[4];
#pragma unroll
    for (int nf = 0; nf < 4; nf++) o[nf] = make_float4(0.f, 0.f, 0.f, 0.f);
    float2 lp = make_float2(0.f, 0.f);

    const float* Bh = bias + (size_t)h * 65536;
    const float* bb0 = Bh + (size_t)(w * 16 + r4) * 256 + 2 * c4;
    const float* bb1 = Bh + (size_t)(w * 16 + r4 + 8) * 256 + 2 * c4;
    float2 bp0 = *(const float2*)(bb0);
    float2 bp1 = *(const float2*)(bb1);

#pragma unroll 1
    for (int kv0 = 0; kv0 < 256; kv0 += 8) {
      const int kt = kv0 >> 3;

      float4 S = make_float4(0.f, 0.f, 0.f, 0.f);
#pragma unroll
      for (int dd = 0; dd < 4; dd++) {
        float2 kp = *(float2*)(Ks + ((kt * 4 + dd) * 32 + lane) * 2);
        mma8(S, qa[dd].x, qa[dd].y, qa[dd].z, qa[dd].w, kp.x, kp.y);
      }

      float2 vp[4];
#pragma unroll
      for (int nf = 0; nf < 4; nf++)
        vp[nf] = *(float2*)(Vs + ((kt * 4 + nf) * 32 + lane) * 2);

      float m0 = ms[kv0 + 2 * c4];
      float m1 = ms[kv0 + 2 * c4 + 1];

      float2 nb0, nb1;
      if (kv0 < 248) {
        nb0 = *(const float2*)(bb0 + kv0 + 8);
        nb1 = *(const float2*)(bb1 + kv0 + 8);
      }

      float p0 = __expf(S.x + bp0.x + m0);
      float p1 = __expf(S.y + bp0.y + m1);
      float p2 = __expf(S.z + bp1.x + m0);
      float p3 = __expf(S.w + bp1.y + m1);
      lp.x += p0 + p1;
      lp.y += p2 + p3;

      float t00 = __shfl_sync(0xffffffffu, p0, src0);
      float t01 = __shfl_sync(0xffffffffu, p1, src0);
      float t20 = __shfl_sync(0xffffffffu, p2, src0);
      float t21 = __shfl_sync(0xffffffffu, p3, src0);
      float u00 = __shfl_sync(0xffffffffu, p0, src2);
      float u01 = __shfl_sync(0xffffffffu, p1, src2);
      float u20 = __shfl_sync(0xffffffffu, p2, src2);
      float u21 = __shfl_sync(0xffffffffu, p3, src2);
      float a0 = odd ? t01 : t00;
      float a1 = odd ? t21 : t20;
      float a2 = odd ? u01 : u00;
      float a3 = odd ? u21 : u20;

#pragma unroll
      for (int nf = 0; nf < 4; nf++)
        mma8(o[nf], a0, a1, a2, a3, vp[nf].x, vp[nf].y);

      if (kv0 < 248) { bp0 = nb0; bp1 = nb1; }
    }

    // ---- normalize O, convert to A-frags, out += O @ Wo_h ----
    lp.x += __shfl_xor_sync(0xffffffffu, lp.x, 1);
    lp.x += __shfl_xor_sync(0xffffffffu, lp.x, 2);
    lp.y += __shfl_xor_sync(0xffffffffu, lp.y, 1);
    lp.y += __shfl_xor_sync(0xffffffffu, lp.y, 2);
    float inv0 = 1.0f / lp.x;
    float inv8 = 1.0f / lp.y;
#pragma unroll
    for (int kk = 0; kk < 4; kk++) {
      float p0 = f2tf(o[kk].x * inv0), p1 = f2tf(o[kk].y * inv0);
      float p2 = f2tf(o[kk].z * inv8), p3 = f2tf(o[kk].w * inv8);
      float t00 = __shfl_sync(0xffffffffu, p0, src0);
      float t01 = __shfl_sync(0xffffffffu, p1, src0);
      float t20 = __shfl_sync(0xffffffffu, p2, src0);
      float t21 = __shfl_sync(0xffffffffu, p3, src0);
      float u00 = __shfl_sync(0xffffffffu, p0, src2);
      float u01 = __shfl_sync(0xffffffffu, p1, src2);
      float u20 = __shfl_sync(0xffffffffu, p2, src2);
      float u21 = __shfl_sync(0xffffffffu, p3, src2);
      float a0 = odd ? t01 : t00;
      float a1 = odd ? t21 : t20;
      float a2 = odd ? u01 : u00;
      float a3 = odd ? u21 : u20;
#pragma unroll
      for (int nf = 0; nf < 8; nf++) {
        float2 B = *(float2*)(Wsm + 6144 + ((kk * 8 + nf) * 32 + lane) * 2);
        mma8(oacc[nf], a0, a1, a2, a3, B.x, B.y);
      }
    }
  }

  // ---- epilogue: + bo, store ----
  {
    int row = s * 256 + w * 16 + r4;
#pragma unroll
    for (int nf = 0; nf < 8; nf++) {
      int col = nf * 8 + 2 * c4;
      float2 bb = *(const float2*)(bo + col);
      *(float2*)(outg + (size_t)row * 64 + col) =
          make_float2(oacc[nf].x + bb.x, oacc[nf].y + bb.y);
      *(float2*)(outg + (size_t)(row + 8) * 64 + col) =
          make_float2(oacc[nf].z + bb.x, oacc[nf].w + bb.y);
    }
  }
}

// ---------------------------------------------------------------------------
extern "C" void kernel_launch(void* const* d_in, const int* in_sizes, int n_in,
                              void* d_out, int out_size) {
  const float* input_q  = (const float*)d_in[0];
  const float* input_kv = (const float*)d_in[1];
  const float* mask     = (const float*)d_in[2];
  const float* bias     = (const float*)d_in[3];
  const float* wq       = (const float*)d_in[4];
  const float* wk       = (const float*)d_in[5];
  const float* wv       = (const float*)d_in[6];
  const float* wo       = (const float*)d_in[7];
  const float* bo       = (const float*)d_in[8];
  float* out = (float*)d_out;

  cudaFuncSetAttribute(fused_kernel, cudaFuncAttributeMaxDynamicSharedMemorySize,
                       FUSED_SMEM);

  prep_kernel<<<64, 256>>>(wq, wk, wv, wo);
  fused_kernel<<<S_LEN, 512, FUSED_SMEM>>>(input_q, input_kv, mask, bias, bo, out);
}

// round 7
// speedup vs baseline: 2.0098x; 2.0098x over previous
#include <cuda_runtime.h>
#include <cuda_fp16.h>

#define S_LEN 128
#define NH 8
#define INF9 1.0e9f

// Weight fragments in fp16 B-frag layout (uint = half2), prepped per launch.
__device__ unsigned g_Wfu[3 * 8 * 1024];   // [z][h][kg4][nf4][lane32][p2]
__device__ unsigned g_Wofu[8 * 1024];      // [h][kg2][nf8][lane32][p2]

__device__ __forceinline__ unsigned pk(float a, float b) {
  __half2 h = __floats2half2_rn(a, b);
  return *(unsigned*)&h;
}

// D += A(16x16 f16) * B(16x8 f16), fp32 accum.
__device__ __forceinline__ void mma16(float4& c, unsigned a0, unsigned a1,
                                      unsigned a2, unsigned a3, unsigned b0,
                                      unsigned b1) {
  asm volatile(
      "mma.sync.aligned.m16n8k16.row.col.f32.f16.f16.f32 "
      "{%0,%1,%2,%3}, {%4,%5,%6,%7}, {%8,%9}, {%0,%1,%2,%3};"
      : "+f"(c.x), "+f"(c.y), "+f"(c.z), "+f"(c.w)
      : "r"(a0), "r"(a1), "r"(a2), "r"(a3), "r"(b0), "r"(b1));
}

// ---------------------------------------------------------------------------
// Prep: weights -> per-head fp16 B-frag layouts (wq pre-scaled by 1/sqrt(32)).
// B-frag: thread(r4,c4) p-th reg = {B[kg*16+2c4+8p][n], B[...+1][n]}, n=nf*8+r4
// ---------------------------------------------------------------------------
__global__ void prep_kernel(const float* __restrict__ wq,
                            const float* __restrict__ wk,
                            const float* __restrict__ wv,
                            const float* __restrict__ wo) {
  const float scale = 0.17677669529663687f;
  for (int id = blockIdx.x * 256 + threadIdx.x; id < 32768; id += 64 * 256) {
    if (id < 24576) {
      int p = id & 1, lane = (id >> 1) & 31, nf = (id >> 6) & 3,
          kg = (id >> 8) & 3, h = (id >> 10) & 7, z = id >> 13;
      int r4 = lane >> 2, c4 = lane & 3;
      const float* w = (z == 0) ? wq : (z == 1) ? wk : wv;
      int k0 = kg * 16 + 2 * c4 + 8 * p;
      int col = h * 32 + nf * 8 + r4;
      float v0 = w[k0 * 256 + col], v1 = w[(k0 + 1) * 256 + col];
      if (z == 0) { v0 *= scale; v1 *= scale; }
      g_Wfu[id] = pk(v0, v1);
    } else {
      int id2 = id - 24576;
      int p = id2 & 1, lane = (id2 >> 1) & 31, nf = (id2 >> 6) & 7,
          kg = (id2 >> 9) & 1, h = id2 >> 10;
      int r4 = lane >> 2, c4 = lane & 3;
      int k0 = kg * 16 + 2 * c4 + 8 * p;
      int col = nf * 8 + r4;
      g_Wofu[id2] = pk(wo[(h * 32 + k0) * 64 + col],
                       wo[(h * 32 + k0 + 1) * 64 + col]);
    }
  }
}

// ---------------------------------------------------------------------------
// Mega-fused kernel: one block per s, 256 threads (8 warps), warp owns 32
// rows (q and kv). fp16 operands everywhere, fp32 accum, zero shuffles in
// the kv loop.
//
// SMEM (uints): Xq[8192] Xk[8192] Wsm[4096] Ks[4096] Vs[4096] ms[256 floats]
// ---------------------------------------------------------------------------
#define XQ_OFF 0
#define XK_OFF 8192
#define WS_OFF 16384
#define KS_OFF 20480
#define VS_OFF 24576
#define MS_OFF 28672
#define FUSED_SMEM ((28672 + 256) * 4)

__global__ __launch_bounds__(256, 1) void fused_kernel(
    const float* __restrict__ xq, const float* __restrict__ xkv,
    const float* __restrict__ mask, const float* __restrict__ bias,
    const float* __restrict__ bo, float* __restrict__ outg) {
  extern __shared__ unsigned smu[];
  float* ms = (float*)(smu + MS_OFF);

  const int tid = threadIdx.x;
  const int s = blockIdx.x;

  // ---- stage Xq, Xkv as fp16 A-frags ----
  // A-frag: reg r (=eR+2*hi) at lane (r4*4+c4) = {X[row][k], X[row][k+1]}
  for (int i = tid; i < 4096; i += 256) {
    int row = i >> 4, k0 = (i & 15) * 4;
    float4 a = *(const float4*)(xq + (size_t)(s * 256 + row) * 64 + k0);
    float4 b = *(const float4*)(xkv + (size_t)(s * 256 + row) * 64 + k0);
    int rt = row >> 4, kg = k0 >> 4;
    int r4s = row & 7, eR = (row >> 3) & 1;
    int pi0 = (k0 & 15) >> 1;           // even
    int c4a = pi0 & 3, hi = pi0 >> 2;
    int reg = eR + 2 * hi;
    int base = (((rt * 4 + kg) * 32 + r4s * 4 + c4a) * 4) + reg;
    smu[XQ_OFF + base] = pk(a.x, a.y);
    smu[XQ_OFF + base + 4] = pk(a.z, a.w);
    smu[XK_OFF + base] = pk(b.x, b.y);
    smu[XK_OFF + base + 4] = pk(b.z, b.w);
  }
  ms[tid] = (mask[s * 256 + tid] - 1.0f) * INF9 - 4.0f;  // -4: exp headroom

  const int w = tid >> 5, lane = tid & 31;
  const int r4 = lane >> 2, c4 = lane & 3;
  const int rt0 = w * 2;

  const uint4* Xq4 = (const uint4*)(smu + XQ_OFF);
  const uint4* Xk4 = (const uint4*)(smu + XK_OFF);
  const uint2* Ws2 = (const uint2*)(smu + WS_OFF);
  const uint2* Ks2 = (const uint2*)(smu + KS_OFF);
  const uint2* Vs2 = (const uint2*)(smu + VS_OFF);

  float4 oacc[2][8];
#pragma unroll
  for (int i = 0; i < 2; i++)
#pragma unroll
    for (int j = 0; j < 8; j++) oacc[i][j] = make_float4(0.f, 0.f, 0.f, 0.f);

#pragma unroll 1
  for (int h = 0; h < NH; h++) {
    __syncthreads();  // prev head's Ks/Vs/Wsm reads done; X staging visible
    // stage W frags: Wq|Wk|Wv|Wo = 1024 uint4
    {
      uint4* dst = (uint4*)(smu + WS_OFF);
#pragma unroll
      for (int i = tid; i < 1024; i += 256) {
        int z = i >> 8, wi = i & 255;
        dst[i] = (z < 3) ? ((const uint4*)g_Wfu)[(z * 8 + h) * 256 + wi]
                         : ((const uint4*)g_Wofu)[h * 256 + wi];
      }
    }
    __syncthreads();

    // ---- Q = Xq @ Wq_h -> qa A-frags (direct pack, no shuffle) ----
    uint4 qa[2][2];
    {
      float4 acc[2][4];
#pragma unroll
      for (int i = 0; i < 2; i++)
#pragma unroll
        for (int j = 0; j < 4; j++) acc[i][j] = make_float4(0.f, 0.f, 0.f, 0.f);
#pragma unroll
      for (int kg = 0; kg < 4; kg++) {
        uint4 A0 = Xq4[(rt0 * 4 + kg) * 32 + lane];
        uint4 A1 = Xq4[((rt0 + 1) * 4 + kg) * 32 + lane];
#pragma unroll
        for (int nf = 0; nf < 4; nf++) {
          uint2 B = Ws2[(kg * 4 + nf) * 32 + lane];
          mma16(acc[0][nf], A0.x, A0.y, A0.z, A0.w, B.x, B.y);
          mma16(acc[1][nf], A1.x, A1.y, A1.z, A1.w, B.x, B.y);
        }
      }
#pragma unroll
      for (int mt = 0; mt < 2; mt++)
#pragma unroll
        for (int kg = 0; kg < 2; kg++)
          qa[mt][kg] = make_uint4(pk(acc[mt][2 * kg].x, acc[mt][2 * kg].y),
                                  pk(acc[mt][2 * kg].z, acc[mt][2 * kg].w),
                                  pk(acc[mt][2 * kg + 1].x, acc[mt][2 * kg + 1].y),
                                  pk(acc[mt][2 * kg + 1].z, acc[mt][2 * kg + 1].w));
    }

    // ---- K = Xkv @ Wk_h -> Ks (B-frag scatter: address collapses to lane) --
    {
      float4 acc[2][4];
#pragma unroll
      for (int i = 0; i < 2; i++)
#pragma unroll
        for (int j = 0; j < 4; j++) acc[i][j] = make_float4(0.f, 0.f, 0.f, 0.f);
#pragma unroll
      for (int kg = 0; kg < 4; kg++) {
        uint4 A0 = Xk4[(rt0 * 4 + kg) * 32 + lane];
        uint4 A1 = Xk4[((rt0 + 1) * 4 + kg) * 32 + lane];
#pragma unroll
        for (int nf = 0; nf < 4; nf++) {
          uint2 B = Ws2[512 + (kg * 4 + nf) * 32 + lane];
          mma16(acc[0][nf], A0.x, A0.y, A0.z, A0.w, B.x, B.y);
          mma16(acc[1][nf], A1.x, A1.y, A1.z, A1.w, B.x, B.y);
        }
      }
#pragma unroll
      for (int mt = 0; mt < 2; mt++) {
        int kt = w * 2 + mt;
#pragma unroll
        for (int nf = 0; nf < 4; nf++) {
          int kgd = nf >> 1, p = nf & 1;
          smu[KS_OFF + (((kt * 2 + kgd) * 2 + 0) * 32 + lane) * 2 + p] =
              pk(acc[mt][nf].x, acc[mt][nf].y);
          smu[KS_OFF + (((kt * 2 + kgd) * 2 + 1) * 32 + lane) * 2 + p] =
              pk(acc[mt][nf].z, acc[mt][nf].w);
        }
      }
    }

    // ---- V = Xkv @ Wv_h -> Vs (scalar half scatter, kv-pairs) ----
    {
      float4 acc[2][4];
#pragma unroll
      for (int i = 0; i < 2; i++)
#pragma unroll
        for (int j = 0; j < 4; j++) acc[i][j] = make_float4(0.f, 0.f, 0.f, 0.f);
#pragma unroll
      for (int kg = 0; kg < 4; kg++) {
        uint4 A0 = Xk4[(rt0 * 4 + kg) * 32 + lane];
        uint4 A1 = Xk4[((rt0 + 1) * 4 + kg) * 32 + lane];
#pragma unroll
        for (int nf = 0; nf < 4; nf++) {
          uint2 B = Ws2[1024 + (kg * 4 + nf) * 32 + lane];
          mma16(acc[0][nf], A0.x, A0.y, A0.z, A0.w, B.x, B.y);
          mma16(acc[1][nf], A1.x, A1.y, A1.z, A1.w, B.x, B.y);
        }
      }
      __half* Vh = (__half*)(smu + VS_OFF);
      int e = r4 & 1, cp = r4 >> 1;
#pragma unroll
      for (int mt = 0; mt < 2; mt++) {
        int kt = w * 2 + mt;
#pragma unroll
        for (int nf = 0; nf < 4; nf++) {
          int b0 = (((kt * 4 + nf) * 32 + (2 * c4) * 4 + cp) * 4) + e;
          int b1 = b0 + 16;  // col +1 -> lane +4 -> halves +16
          Vh[b0] = __float2half_rn(acc[mt][nf].x);
          Vh[b0 + 2] = __float2half_rn(acc[mt][nf].z);
          Vh[b1] = __float2half_rn(acc[mt][nf].y);
          Vh[b1 + 2] = __float2half_rn(acc[mt][nf].w);
        }
      }
    }
    __syncthreads();  // Ks/Vs ready

    // ---- attention ----
    float4 o[2][4];
#pragma unroll
    for (int mt = 0; mt < 2; mt++)
#pragma unroll
      for (int nf = 0; nf < 4; nf++) o[mt][nf] = make_float4(0.f, 0.f, 0.f, 0.f);
    float2 lp[2] = {make_float2(0.f, 0.f), make_float2(0.f, 0.f)};

    const float* Bh = bias + (size_t)h * 65536;
    const float* bb0[2]; const float* bb1[2];
#pragma unroll
    for (int mt = 0; mt < 2; mt++) {
      bb0[mt] = Bh + (size_t)(w * 32 + mt * 16 + r4) * 256 + 2 * c4;
      bb1[mt] = Bh + (size_t)(w * 32 + mt * 16 + r4 + 8) * 256 + 2 * c4;
    }
    float2 cb[2][2][2];  // [mt][nt][rowpair]
#pragma unroll
    for (int mt = 0; mt < 2; mt++)
#pragma unroll
      for (int nt = 0; nt < 2; nt++) {
        cb[mt][nt][0] = *(const float2*)(bb0[mt] + nt * 8);
        cb[mt][nt][1] = *(const float2*)(bb1[mt] + nt * 8);
      }

#pragma unroll 1
    for (int kt = 0; kt < 16; kt++) {
      const int kv0 = kt * 16;

      // prefetch next chunk's bias
      float2 nb[2][2][2];
      if (kt < 15) {
#pragma unroll
        for (int mt = 0; mt < 2; mt++)
#pragma unroll
          for (int nt = 0; nt < 2; nt++) {
            nb[mt][nt][0] = *(const float2*)(bb0[mt] + kv0 + 16 + nt * 8);
            nb[mt][nt][1] = *(const float2*)(bb1[mt] + kv0 + 16 + nt * 8);
          }
      }

      float2 m0 = *(const float2*)(ms + kv0 + 2 * c4);
      float2 m1 = *(const float2*)(ms + kv0 + 8 + 2 * c4);

      // S init with bias+mask (mma C input)
      float4 Sf[2][2];
#pragma unroll
      for (int mt = 0; mt < 2; mt++) {
        Sf[mt][0] = make_float4(cb[mt][0][0].x + m0.x, cb[mt][0][0].y + m0.y,
                                cb[mt][0][1].x + m0.x, cb[mt][0][1].y + m0.y);
        Sf[mt][1] = make_float4(cb[mt][1][0].x + m1.x, cb[mt][1][0].y + m1.y,
                                cb[mt][1][1].x + m1.x, cb[mt][1][1].y + m1.y);
      }

#pragma unroll
      for (int kg = 0; kg < 2; kg++) {
        uint2 Kb0 = Ks2[((kt * 2 + kg) * 2 + 0) * 32 + lane];
        uint2 Kb1 = Ks2[((kt * 2 + kg) * 2 + 1) * 32 + lane];
#pragma unroll
        for (int mt = 0; mt < 2; mt++) {
          mma16(Sf[mt][0], qa[mt][kg].x, qa[mt][kg].y, qa[mt][kg].z,
                qa[mt][kg].w, Kb0.x, Kb0.y);
          mma16(Sf[mt][1], qa[mt][kg].x, qa[mt][kg].y, qa[mt][kg].z,
                qa[mt][kg].w, Kb1.x, Kb1.y);
        }
      }

      uint2 Vb[4];
#pragma unroll
      for (int nf = 0; nf < 4; nf++) Vb[nf] = Vs2[(kt * 4 + nf) * 32 + lane];

#pragma unroll
      for (int mt = 0; mt < 2; mt++) {
        float p00 = __expf(Sf[mt][0].x), p01 = __expf(Sf[mt][0].y);
        float p02 = __expf(Sf[mt][0].z), p03 = __expf(Sf[mt][0].w);
        float p10 = __expf(Sf[mt][1].x), p11 = __expf(Sf[mt][1].y);
        float p12 = __expf(Sf[mt][1].z), p13 = __expf(Sf[mt][1].w);
        lp[mt].x += (p00 + p01) + (p10 + p11);
        lp[mt].y += (p02 + p03) + (p12 + p13);
        unsigned pa0 = pk(p00, p01), pa1 = pk(p02, p03);
        unsigned pa2 = pk(p10, p11), pa3 = pk(p12, p13);
#pragma unroll
        for (int nf = 0; nf < 4; nf++)
          mma16(o[mt][nf], pa0, pa1, pa2, pa3, Vb[nf].x, Vb[nf].y);
      }

      if (kt < 15) {
#pragma unroll
        for (int mt = 0; mt < 2; mt++)
#pragma unroll
          for (int nt = 0; nt < 2; nt++) {
            cb[mt][nt][0] = nb[mt][nt][0];
            cb[mt][nt][1] = nb[mt][nt][1];
          }
      }
    }

    // ---- normalize O, pack to A-frags, oacc += O @ Wo_h ----
#pragma unroll
    for (int mt = 0; mt < 2; mt++) {
      lp[mt].x += __shfl_xor_sync(0xffffffffu, lp[mt].x, 1);
      lp[mt].x += __shfl_xor_sync(0xffffffffu, lp[mt].x, 2);
      lp[mt].y += __shfl_xor_sync(0xffffffffu, lp[mt].y, 1);
      lp[mt].y += __shfl_xor_sync(0xffffffffu, lp[mt].y, 2);
      float inv0 = 1.0f / lp[mt].x;
      float inv8 = 1.0f / lp[mt].y;
#pragma unroll
      for (int kg = 0; kg < 2; kg++) {
        unsigned oa0 = pk(o[mt][2 * kg].x * inv0, o[mt][2 * kg].y * inv0);
        unsigned oa1 = pk(o[mt][2 * kg].z * inv8, o[mt][2 * kg].w * inv8);
        unsigned oa2 = pk(o[mt][2 * kg + 1].x * inv0, o[mt][2 * kg + 1].y * inv0);
        unsigned oa3 = pk(o[mt][2 * kg + 1].z * inv8, o[mt][2 * kg + 1].w * inv8);
#pragma unroll
        for (int nf = 0; nf < 8; nf++) {
          uint2 B = Ws2[1536 + (kg * 8 + nf) * 32 + lane];
          mma16(oacc[mt][nf], oa0, oa1, oa2, oa3, B.x, B.y);
        }
      }
    }
  }

  // ---- epilogue: + bo, store ----
#pragma unroll
  for (int mt = 0; mt < 2; mt++) {
    int row = s * 256 + w * 32 + mt * 16 + r4;
#pragma unroll
    for (int nf = 0; nf < 8; nf++) {
      int col = nf * 8 + 2 * c4;
      float2 bb = *(const float2*)(bo + col);
      *(float2*)(outg + (size_t)row * 64 + col) =
          make_float2(oacc[mt][nf].x + bb.x, oacc[mt][nf].y + bb.y);
      *(float2*)(outg + (size_t)(row + 8) * 64 + col) =
          make_float2(oacc[mt][nf].z + bb.x, oacc[mt][nf].w + bb.y);
    }
  }
}

// ---------------------------------------------------------------------------
extern "C" void kernel_launch(void* const* d_in, const int* in_sizes, int n_in,
                              void* d_out, int out_size) {
  const float* input_q  = (const float*)d_in[0];
  const float* input_kv = (const float*)d_in[1];
  const float* mask     = (const float*)d_in[2];
  const float* bias     = (const float*)d_in[3];
  const float* wq       = (const float*)d_in[4];
  const float* wk       = (const float*)d_in[5];
  const float* wv       = (const float*)d_in[6];
  const float* wo       = (const float*)d_in[7];
  const float* bo       = (const float*)d_in[8];
  float* out = (float*)d_out;

  cudaFuncSetAttribute(fused_kernel, cudaFuncAttributeMaxDynamicSharedMemorySize,
                       FUSED_SMEM);

  prep_kernel<<<64, 256>>>(wq, wk, wv, wo);
  fused_kernel<<<S_LEN, 256, FUSED_SMEM>>>(input_q, input_kv, mask, bias, bo, out);
}